// round 16
// baseline (speedup 1.0000x reference)
#include <cuda_runtime.h>
#include <cuda_bf16.h>
#include <math.h>
#include <float.h>
#include <stdint.h>

#define NI 128
#define NC 256
#define RR 36
#define WW 48
#define DD 256

#define MROWS (NI*RR)     // 4608
#define NCOLS (NC*WW)     // 12288

typedef unsigned long long u64;

// ---------------- device scratch ----------------
__device__ __align__(16) __nv_bfloat16 g_Ahi[MROWS * DD];
__device__ __align__(16) __nv_bfloat16 g_Alo[MROWS * DD];
__device__ __align__(16) __nv_bfloat16 g_Bhi[NCOLS * DD];
__device__ __align__(16) __nv_bfloat16 g_Blo[NCOLS * DD];
__device__ __align__(16) float g_S[(size_t)MROWS * NCOLS];   // 226 MB
__device__ __align__(16) float g_capnorm[NC * WW];
__device__ __align__(16) float2 g_gram2[NI * RR * RR];       // duplicated-pair Gram

// ---------------- PTX helpers ----------------
__device__ __forceinline__ uint32_t smem_u32(const void* p) {
    uint32_t a;
    asm("{ .reg .u64 t; cvta.to.shared.u64 t, %1; cvt.u32.u64 %0, t; }" : "=r"(a) : "l"(p));
    return a;
}
__device__ __forceinline__ void cpa16(uint32_t dst, const void* src) {
    asm volatile("cp.async.cg.shared.global [%0], [%1], 16;" :: "r"(dst), "l"(src));
}
__device__ __forceinline__ void cpa_commit() {
    asm volatile("cp.async.commit_group;" ::: "memory");
}
template<int N> __device__ __forceinline__ void cpa_wait() {
    asm volatile("cp.async.wait_group %0;" :: "n"(N) : "memory");
}
__device__ __forceinline__ void ldsm4(uint32_t* r, uint32_t addr) {
    asm volatile("ldmatrix.sync.aligned.m8n8.x4.shared.b16 {%0,%1,%2,%3}, [%4];"
                 : "=r"(r[0]), "=r"(r[1]), "=r"(r[2]), "=r"(r[3]) : "r"(addr));
}
__device__ __forceinline__ void mma_bf16(float* d, const uint32_t* a, const uint32_t* b) {
    asm volatile(
        "mma.sync.aligned.m16n8k16.row.col.f32.bf16.bf16.f32 "
        "{%0,%1,%2,%3}, {%4,%5,%6,%7}, {%8,%9}, {%0,%1,%2,%3};"
        : "+f"(d[0]), "+f"(d[1]), "+f"(d[2]), "+f"(d[3])
        : "r"(a[0]), "r"(a[1]), "r"(a[2]), "r"(a[3]), "r"(b[0]), "r"(b[1]));
}
__device__ __forceinline__ void ffma2(u64& d, u64 a, u64 b) {
    asm("fma.rn.f32x2 %0, %1, %2, %0;" : "+l"(d) : "l"(a), "l"(b));
}
__device__ __forceinline__ float2 unpk(u64 v) {
    float2 r; asm("mov.b64 {%0, %1}, %2;" : "=f"(r.x), "=f"(r.y) : "l"(v)); return r;
}
__device__ __forceinline__ void stcs2(float* p, float2 v) {
    asm volatile("st.global.cs.v2.f32 [%0], {%1, %2};" :: "l"(p), "f"(v.x), "f"(v.y) : "memory");
}

// ---------------- pre-kernels ----------------
__global__ void decomp_kernel(const float* __restrict__ images,
                              const float* __restrict__ captions) {
    int stride = gridDim.x * blockDim.x;
    int g = blockIdx.x * blockDim.x + threadIdx.x;
    for (int idx = g; idx < MROWS * DD; idx += stride) {
        float x = images[idx];
        __nv_bfloat16 h = __float2bfloat16(x);
        g_Ahi[idx] = h;
        g_Alo[idx] = __float2bfloat16(x - __bfloat162float(h));
    }
    for (int idx = g; idx < NCOLS * DD; idx += stride) {
        float x = captions[idx];
        __nv_bfloat16 h = __float2bfloat16(x);
        g_Bhi[idx] = h;
        g_Blo[idx] = __float2bfloat16(x - __bfloat162float(h));
    }
}

__global__ void capnorm_kernel(const float* __restrict__ captions) {
    int row = blockIdx.x * 8 + (threadIdx.x >> 5);
    int lane = threadIdx.x & 31;
    const float4* p = (const float4*)(captions + (size_t)row * DD);
    float4 a = p[lane * 2], b = p[lane * 2 + 1];
    float ss = a.x*a.x + a.y*a.y + a.z*a.z + a.w*a.w
             + b.x*b.x + b.y*b.y + b.z*b.z + b.w*b.w;
    #pragma unroll
    for (int off = 16; off; off >>= 1)
        ss += __shfl_xor_sync(0xffffffffu, ss, off);
    if (lane == 0) g_capnorm[row] = sqrtf(ss);
}

#define GIMG_STR 260
__global__ void gram_kernel(const float* __restrict__ images) {
    __shared__ float s_img[RR * GIMG_STR];
    const int i = blockIdx.x;
    const float4* src = (const float4*)(images + (size_t)i * RR * DD);
    for (int idx = threadIdx.x; idx < RR * DD / 4; idx += blockDim.x) {
        float4 v = src[idx];
        int r = idx >> 6;
        int d = (idx & 63) << 2;
        *(float4*)(s_img + r * GIMG_STR + d) = v;
    }
    __syncthreads();
    for (int e = threadIdx.x; e < RR * RR; e += blockDim.x) {
        int k1 = e / RR, k2 = e % RR;
        const float4* p = (const float4*)(s_img + k1 * GIMG_STR);
        const float4* q = (const float4*)(s_img + k2 * GIMG_STR);
        float s = 0.f;
        #pragma unroll 8
        for (int d = 0; d < DD / 4; ++d) {
            float4 a = p[d], b = q[d];
            s = fmaf(a.x, b.x, s); s = fmaf(a.y, b.y, s);
            s = fmaf(a.z, b.z, s); s = fmaf(a.w, b.w, s);
        }
        float2 dup = {s, s};
        g_gram2[(size_t)i * RR * RR + e] = dup;
    }
}

// ---------------- GEMM: R13 verbatim (2-stage, wait<1>, 80B stride, 2 CTAs/SM) ----------------
#define GT 256
#define TSTR_B 80
#define TILE_BYTES (128 * TSTR_B)              // 10240
#define GSMEM_TOTAL (8 * TILE_BYTES)           // 81920

__global__ void __launch_bounds__(GT, 2) gemm_kernel() {
    extern __shared__ char smem[];
    const uint32_t sb = smem_u32(smem);
    const int tid = threadIdx.x;
    const int wid = tid >> 5, lane = tid & 31;
    const int ntile = blockIdx.x;
    const int mtile = blockIdx.y;

    const __nv_bfloat16* gsrc[4] = {
        g_Ahi + (size_t)(mtile * 128) * DD,
        g_Alo + (size_t)(mtile * 128) * DD,
        g_Bhi + (size_t)(ntile * 128) * DD,
        g_Blo + (size_t)(ntile * 128) * DD
    };

    auto issue = [&](int kc) {
        const uint32_t bufbase = sb + (uint32_t)(kc & 1) * 4 * TILE_BYTES;
        #pragma unroll
        for (int p = 0; p < 8; p++) {
            int idx = tid + p * GT;
            int tile = idx >> 9, rem = idx & 511;
            int r = rem >> 2, j = rem & 3;
            const __nv_bfloat16* src = gsrc[tile] + (size_t)r * DD + kc * 32 + j * 8;
            uint32_t dst = bufbase + tile * TILE_BYTES + r * TSTR_B + j * 16;
            cpa16(dst, src);
        }
        cpa_commit();
    };

    const int wm = wid >> 2, wn = wid & 3;

    float acc[4][4][4];
    #pragma unroll
    for (int f = 0; f < 4; f++)
        #pragma unroll
        for (int nf = 0; nf < 4; nf++)
            #pragma unroll
            for (int e = 0; e < 4; e++) acc[f][nf][e] = 0.f;

    issue(0);
    for (int kc = 0; kc < 8; kc++) {
        if (kc < 7) { issue(kc + 1); cpa_wait<1>(); }
        else        { cpa_wait<0>(); }
        __syncthreads();

        const uint32_t abase = sb + (uint32_t)(kc & 1) * 4 * TILE_BYTES;
        const uint32_t bbase = abase + 2 * TILE_BYTES;

        #pragma unroll
        for (int s = 0; s < 2; s++) {
            uint32_t bh[8], bl[8];
            {
                int bn = wn * 32 + (lane & 7) + ((lane >> 4) << 3);
                uint32_t bcol = s * 32 + ((lane >> 3) & 1) * 16;
                #pragma unroll
                for (int g = 0; g < 2; g++) {
                    uint32_t addr = bbase + (uint32_t)(bn + g * 16) * TSTR_B + bcol;
                    ldsm4(&bh[g * 4], addr);
                    ldsm4(&bl[g * 4], addr + TILE_BYTES);
                }
            }
            int ar = wm * 64 + (lane & 15);
            uint32_t acol = s * 32 + (lane >> 4) * 16;
            #pragma unroll
            for (int f = 0; f < 4; f++) {
                uint32_t aaddr = abase + (uint32_t)(ar + f * 16) * TSTR_B + acol;
                uint32_t ah[4], al[4];
                ldsm4(ah, aaddr);
                ldsm4(al, aaddr + TILE_BYTES);
                #pragma unroll
                for (int nf = 0; nf < 4; nf++) {
                    mma_bf16(acc[f][nf], ah, &bh[nf * 2]);
                    mma_bf16(acc[f][nf], ah, &bl[nf * 2]);
                    mma_bf16(acc[f][nf], al, &bh[nf * 2]);
                }
            }
        }
        __syncthreads();
    }

    float* obase = g_S + (size_t)(mtile * 128) * NCOLS + ntile * 128;
    const int r0 = wm * 64 + (lane >> 2);
    const int c0 = wn * 32 + (lane & 3) * 2;
    #pragma unroll
    for (int f = 0; f < 4; f++) {
        #pragma unroll
        for (int nf = 0; nf < 4; nf++) {
            int r = r0 + f * 16, cc = c0 + nf * 8;
            float2 v0 = { acc[f][nf][0], acc[f][nf][1] };
            float2 v1 = { acc[f][nf][2], acc[f][nf][3] };
            stcs2(obase + (size_t)r * NCOLS + cc, v0);
            stcs2(obase + (size_t)(r + 8) * NCOLS + cc, v1);
        }
    }
}

// ---------------- epilogue v8: v7 + pre-duplicated G2 (no dup2 MOVs) ----------------
#define ET 256
#define SSTR 52
#define NTILE (RR * SSTR)       // 1872
#define EOFF_G    0                          // G2: 1296 u64 = 2592 floats
#define EOFF_S    2592                       // 8 * 1872 = 14976
#define EOFF_RINV (EOFF_S + 8*NTILE)         // 288
#define EOFF_RS   (EOFF_RINV + 288)          // 384
#define EOFF_CN   (EOFF_RS + 384)            // 384
#define ESMEM_FLOATS (EOFF_CN + 384)         // 18624 floats = 74496 B

extern __shared__ float esm[];

__global__ void __launch_bounds__(ET, 3) epi_kernel(float* __restrict__ out) {
    const int cg = blockIdx.x;
    const int i  = blockIdx.y;
    const int t  = threadIdx.x;
    const int lane = t & 31, wj = t >> 5;
    const int c0 = cg * 8;

    float* Gs    = esm + EOFF_G;             // u64-dup'd G
    float* Stl   = esm + EOFF_S;
    float* rinvS = esm + EOFF_RINV;
    float* rsS   = esm + EOFF_RS;
    float* cnS   = esm + EOFF_CN;
    const uint32_t sbase = smem_u32(esm);

    // ---- group 1: S tile via cp.async ----
    {
        const float* srow = g_S + (size_t)(i * RR) * NCOLS + (size_t)c0 * WW;
        for (int idx = t; idx < RR * 96; idx += ET) {
            int r = idx / 96, rem = idx % 96;
            int j = rem / 12, q = rem % 12;
            cpa16(sbase + (EOFF_S + j * NTILE + r * SSTR + q * 4) * 4,
                  srow + (size_t)r * NCOLS + j * WW + q * 4);
        }
        cpa_commit();
    }
    // ---- group 2: G2 + capnorms via cp.async ----
    {
        const float* gsrc = (const float*)(g_gram2 + (size_t)i * RR * RR);
        for (int idx = t; idx < RR * RR / 2; idx += ET)     // 648 x 16B = 2592 floats
            cpa16(sbase + (EOFF_G + idx * 4) * 4, gsrc + idx * 4);
        const float* cn = g_capnorm + c0 * WW;
        for (int idx = t; idx < 8 * WW / 4; idx += ET)
            cpa16(sbase + (EOFF_CN + idx * 4) * 4, cn + idx * 4);
        cpa_commit();
    }

    cpa_wait<1>();            // S tile landed
    __syncthreads();

    // ---- rinv9 = 9/(||leaky row||+eps) ----
    for (int row = t; row < 8 * RR; row += ET) {
        int j = row / RR, r = row % RR;
        const float4* sp = (const float4*)(Stl + j * NTILE + r * SSTR);
        float ss = 0.f;
        #pragma unroll
        for (int q = 0; q < 12; q++) {
            float4 a = sp[q];
            float v;
            v = (a.x >= 0.f) ? a.x : 0.1f * a.x; ss = fmaf(v, v, ss);
            v = (a.y >= 0.f) ? a.y : 0.1f * a.y; ss = fmaf(v, v, ss);
            v = (a.z >= 0.f) ? a.z : 0.1f * a.z; ss = fmaf(v, v, ss);
            v = (a.w >= 0.f) ? a.w : 0.1f * a.w; ss = fmaf(v, v, ss);
        }
        rinvS[j * RR + r] = 9.f / (sqrtf(ss) + 1e-8f);
    }
    __syncthreads();

    // ---- per-warp phases; warp wj owns pair (i, c0+wj) ----
    float* Sw = Stl + wj * NTILE;
    const float* rv = rinvS + wj * RR;
    const int l3 = lane & 3;
    const int wl = lane >> 2;

    // Phase A: softmax per column; write unnormalized e over S (disjoint cells)
    float s6[6], w126[6];
    #pragma unroll 1
    for (int q = 0; q < 6; q++) {
        const int w = wl * 6 + q;
        float e9[9];
        float s = 0.f, w12p = 0.f;
        #pragma unroll
        for (int jj = 0; jj < 9; jj++) {
            int r = l3 * 9 + jj;
            float sraw = Sw[r * SSTR + w];
            float v = (sraw >= 0.f) ? sraw : 0.1f * sraw;
            float e = __expf(v * rv[r]);
            e9[jj] = e;
            s += e;
            w12p = fmaf(e, sraw, w12p);
        }
        s    += __shfl_xor_sync(0xffffffffu, s, 1);
        s    += __shfl_xor_sync(0xffffffffu, s, 2);
        w12p += __shfl_xor_sync(0xffffffffu, w12p, 1);
        w12p += __shfl_xor_sync(0xffffffffu, w12p, 2);
        s6[q] = s;
        w126[q] = w12p;
        #pragma unroll
        for (int jj = 0; jj < 9; jj++)
            Sw[(l3 * 9 + jj) * SSTR + w] = e9[jj];
    }
    cpa_wait<0>();            // G2 + cn landed (overlapped with rinv + phase A)
    __syncthreads();

    // Phase B/C split into two jj-halves (register cap); G2 gives dup'd pairs via LDS.64
    const u64* G2u = (const u64*)Gs;
    u64 w2p[3] = {0ull, 0ull, 0ull};

    // ---- half 1: jj in [0,5) ----
    {
        u64 acc[5][3];
        #pragma unroll
        for (int jj = 0; jj < 5; jj++)
            #pragma unroll
            for (int p = 0; p < 3; p++) acc[jj][p] = 0ull;

        #pragma unroll 4
        for (int l = 0; l < RR; l++) {
            const float* Erow = Sw + l * SSTR + wl * 6;
            u64 ep0 = *(const u64*)(Erow);
            u64 ep1 = *(const u64*)(Erow + 2);
            u64 ep2 = *(const u64*)(Erow + 4);
            const u64* gcol = G2u + (l3 * 9) * RR + l;
            #pragma unroll
            for (int jj = 0; jj < 5; jj++) {
                u64 g2 = gcol[jj * RR];
                ffma2(acc[jj][0], g2, ep0);
                ffma2(acc[jj][1], g2, ep1);
                ffma2(acc[jj][2], g2, ep2);
            }
        }
        #pragma unroll
        for (int jj = 0; jj < 5; jj++) {
            const float* Ek = Sw + (l3 * 9 + jj) * SSTR + wl * 6;
            ffma2(w2p[0], *(const u64*)(Ek),     acc[jj][0]);
            ffma2(w2p[1], *(const u64*)(Ek + 2), acc[jj][1]);
            ffma2(w2p[2], *(const u64*)(Ek + 4), acc[jj][2]);
        }
    }
    // ---- half 2: jj in [5,9) ----
    {
        u64 acc[4][3];
        #pragma unroll
        for (int jj = 0; jj < 4; jj++)
            #pragma unroll
            for (int p = 0; p < 3; p++) acc[jj][p] = 0ull;

        #pragma unroll 4
        for (int l = 0; l < RR; l++) {
            const float* Erow = Sw + l * SSTR + wl * 6;
            u64 ep0 = *(const u64*)(Erow);
            u64 ep1 = *(const u64*)(Erow + 2);
            u64 ep2 = *(const u64*)(Erow + 4);
            const u64* gcol = G2u + (l3 * 9 + 5) * RR + l;
            #pragma unroll
            for (int jj = 0; jj < 4; jj++) {
                u64 g2 = gcol[jj * RR];
                ffma2(acc[jj][0], g2, ep0);
                ffma2(acc[jj][1], g2, ep1);
                ffma2(acc[jj][2], g2, ep2);
            }
        }
        #pragma unroll
        for (int jj = 0; jj < 4; jj++) {
            const float* Ek = Sw + (l3 * 9 + 5 + jj) * SSTR + wl * 6;
            ffma2(w2p[0], *(const u64*)(Ek),     acc[jj][0]);
            ffma2(w2p[1], *(const u64*)(Ek + 2), acc[jj][1]);
            ffma2(w2p[2], *(const u64*)(Ek + 4), acc[jj][2]);
        }
    }

    float w2[6];
    {
        float2 a = unpk(w2p[0]), b = unpk(w2p[1]), c = unpk(w2p[2]);
        w2[0] = a.x; w2[1] = a.y; w2[2] = b.x; w2[3] = b.y; w2[4] = c.x; w2[5] = c.y;
    }
    #pragma unroll
    for (int q = 0; q < 6; q++) {
        w2[q] += __shfl_xor_sync(0xffffffffu, w2[q], 1);
        w2[q] += __shfl_xor_sync(0xffffffffu, w2[q], 2);
    }

    if (l3 == 0) {
        #pragma unroll
        for (int q = 0; q < 6; q++) {
            const int w = wl * 6 + q;
            float is = 1.f / s6[q];
            float w12v = w126[q] * is;
            float w2v = sqrtf(fmaxf(w2[q], 0.f)) * is;
            float denom = fmaxf(cnS[wj * WW + w] * w2v, 1e-8f);
            rsS[wj * WW + w] = (w12v / denom) * 6.f;
        }
    }
    __syncwarp();

    // ---- per-warp LogSumExp over 48 words ----
    {
        const float* r = rsS + wj * WW;
        float s = __expf(r[lane]);
        if (lane < 16) s += __expf(r[32 + lane]);
        #pragma unroll
        for (int off = 16; off; off >>= 1)
            s += __shfl_xor_sync(0xffffffffu, s, off);
        if (lane == 0)
            out[(size_t)i * NC + (c0 + wj)] = logf(s) * (1.f / 6.f);
    }
}

extern "C" void kernel_launch(void* const* d_in, const int* in_sizes, int n_in,
                              void* d_out, int out_size)
{
    const float* images   = (const float*)d_in[0];   // (128, 36, 256) fp32
    const float* captions = (const float*)d_in[1];   // (256, 48, 256) fp32
    float* out = (float*)d_out;                       // (128, 256) fp32

    decomp_kernel<<<512, 256>>>(images, captions);
    capnorm_kernel<<<NCOLS / 8, 256>>>(captions);
    gram_kernel<<<NI, 256>>>(images);

    cudaFuncSetAttribute(gemm_kernel,
                         cudaFuncAttributeMaxDynamicSharedMemorySize, GSMEM_TOTAL);
    dim3 ggrid(NCOLS / 128, MROWS / 128);   // 96 x 36
    gemm_kernel<<<ggrid, GT, GSMEM_TOTAL>>>();

    cudaFuncSetAttribute(epi_kernel,
                         cudaFuncAttributeMaxDynamicSharedMemorySize,
                         ESMEM_FLOATS * (int)sizeof(float));
    dim3 egrid(NC / 8, NI);                 // 32 x 128
    epi_kernel<<<egrid, ET, ESMEM_FLOATS * sizeof(float)>>>(out);
}

// round 17
// speedup vs baseline: 1.0705x; 1.0705x over previous
#include <cuda_runtime.h>
#include <cuda_bf16.h>
#include <math.h>
#include <float.h>
#include <stdint.h>

#define NI 128
#define NC 256
#define RR 36
#define WW 48
#define DD 256

#define MROWS (NI*RR)     // 4608
#define NCOLS (NC*WW)     // 12288

typedef unsigned long long u64;

// ---------------- device scratch ----------------
__device__ __align__(16) __nv_bfloat16 g_Ahi[MROWS * DD];
__device__ __align__(16) __nv_bfloat16 g_Alo[MROWS * DD];
__device__ __align__(16) __nv_bfloat16 g_Bhi[NCOLS * DD];
__device__ __align__(16) __nv_bfloat16 g_Blo[NCOLS * DD];
__device__ __align__(16) float g_S[(size_t)MROWS * NCOLS];   // 226 MB
__device__ __align__(16) float g_capnorm[NC * WW];
__device__ __align__(16) float g_gram[NI * RR * RR];

// ---------------- PTX helpers ----------------
__device__ __forceinline__ uint32_t smem_u32(const void* p) {
    uint32_t a;
    asm("{ .reg .u64 t; cvta.to.shared.u64 t, %1; cvt.u32.u64 %0, t; }" : "=r"(a) : "l"(p));
    return a;
}
__device__ __forceinline__ void cpa16(uint32_t dst, const void* src) {
    asm volatile("cp.async.cg.shared.global [%0], [%1], 16;" :: "r"(dst), "l"(src));
}
__device__ __forceinline__ void cpa_commit() {
    asm volatile("cp.async.commit_group;" ::: "memory");
}
template<int N> __device__ __forceinline__ void cpa_wait() {
    asm volatile("cp.async.wait_group %0;" :: "n"(N) : "memory");
}
__device__ __forceinline__ void ldsm4(uint32_t* r, uint32_t addr) {
    asm volatile("ldmatrix.sync.aligned.m8n8.x4.shared.b16 {%0,%1,%2,%3}, [%4];"
                 : "=r"(r[0]), "=r"(r[1]), "=r"(r[2]), "=r"(r[3]) : "r"(addr));
}
__device__ __forceinline__ void mma_bf16(float* d, const uint32_t* a, const uint32_t* b) {
    asm volatile(
        "mma.sync.aligned.m16n8k16.row.col.f32.bf16.bf16.f32 "
        "{%0,%1,%2,%3}, {%4,%5,%6,%7}, {%8,%9}, {%0,%1,%2,%3};"
        : "+f"(d[0]), "+f"(d[1]), "+f"(d[2]), "+f"(d[3])
        : "r"(a[0]), "r"(a[1]), "r"(a[2]), "r"(a[3]), "r"(b[0]), "r"(b[1]));
}
__device__ __forceinline__ u64 dup2(float x) {
    u64 r; asm("mov.b64 %0, {%1, %1};" : "=l"(r) : "f"(x)); return r;
}
__device__ __forceinline__ void ffma2(u64& d, u64 a, u64 b) {
    asm("fma.rn.f32x2 %0, %1, %2, %0;" : "+l"(d) : "l"(a), "l"(b));
}
__device__ __forceinline__ float2 unpk(u64 v) {
    float2 r; asm("mov.b64 {%0, %1}, %2;" : "=f"(r.x), "=f"(r.y) : "l"(v)); return r;
}
__device__ __forceinline__ void stcs2(float* p, float2 v) {
    asm volatile("st.global.cs.v2.f32 [%0], {%1, %2};" :: "l"(p), "f"(v.x), "f"(v.y) : "memory");
}

// ---------------- pre-kernels ----------------
__global__ void decomp_kernel(const float* __restrict__ images,
                              const float* __restrict__ captions) {
    int stride = gridDim.x * blockDim.x;
    int g = blockIdx.x * blockDim.x + threadIdx.x;
    for (int idx = g; idx < MROWS * DD; idx += stride) {
        float x = images[idx];
        __nv_bfloat16 h = __float2bfloat16(x);
        g_Ahi[idx] = h;
        g_Alo[idx] = __float2bfloat16(x - __bfloat162float(h));
    }
    for (int idx = g; idx < NCOLS * DD; idx += stride) {
        float x = captions[idx];
        __nv_bfloat16 h = __float2bfloat16(x);
        g_Bhi[idx] = h;
        g_Blo[idx] = __float2bfloat16(x - __bfloat162float(h));
    }
}

__global__ void capnorm_kernel(const float* __restrict__ captions) {
    int row = blockIdx.x * 8 + (threadIdx.x >> 5);
    int lane = threadIdx.x & 31;
    const float4* p = (const float4*)(captions + (size_t)row * DD);
    float4 a = p[lane * 2], b = p[lane * 2 + 1];
    float ss = a.x*a.x + a.y*a.y + a.z*a.z + a.w*a.w
             + b.x*b.x + b.y*b.y + b.z*b.z + b.w*b.w;
    #pragma unroll
    for (int off = 16; off; off >>= 1)
        ss += __shfl_xor_sync(0xffffffffu, ss, off);
    if (lane == 0) g_capnorm[row] = sqrtf(ss);
}

#define GIMG_STR 260
__global__ void gram_kernel(const float* __restrict__ images) {
    __shared__ float s_img[RR * GIMG_STR];
    const int i = blockIdx.x;
    const float4* src = (const float4*)(images + (size_t)i * RR * DD);
    for (int idx = threadIdx.x; idx < RR * DD / 4; idx += blockDim.x) {
        float4 v = src[idx];
        int r = idx >> 6;
        int d = (idx & 63) << 2;
        *(float4*)(s_img + r * GIMG_STR + d) = v;
    }
    __syncthreads();
    for (int e = threadIdx.x; e < RR * RR; e += blockDim.x) {
        int k1 = e / RR, k2 = e % RR;
        const float4* p = (const float4*)(s_img + k1 * GIMG_STR);
        const float4* q = (const float4*)(s_img + k2 * GIMG_STR);
        float s = 0.f;
        #pragma unroll 8
        for (int d = 0; d < DD / 4; ++d) {
            float4 a = p[d], b = q[d];
            s = fmaf(a.x, b.x, s); s = fmaf(a.y, b.y, s);
            s = fmaf(a.z, b.z, s); s = fmaf(a.w, b.w, s);
        }
        g_gram[(size_t)i * RR * RR + e] = s;
    }
}

// ---------------- GEMM: R13 verbatim (2-stage, wait<1>, 80B stride, 2 CTAs/SM) ----------------
#define GT 256
#define TSTR_B 80
#define TILE_BYTES (128 * TSTR_B)              // 10240
#define GSMEM_TOTAL (8 * TILE_BYTES)           // 81920

__global__ void __launch_bounds__(GT, 2) gemm_kernel() {
    extern __shared__ char smem[];
    const uint32_t sb = smem_u32(smem);
    const int tid = threadIdx.x;
    const int wid = tid >> 5, lane = tid & 31;
    const int ntile = blockIdx.x;
    const int mtile = blockIdx.y;

    const __nv_bfloat16* gsrc[4] = {
        g_Ahi + (size_t)(mtile * 128) * DD,
        g_Alo + (size_t)(mtile * 128) * DD,
        g_Bhi + (size_t)(ntile * 128) * DD,
        g_Blo + (size_t)(ntile * 128) * DD
    };

    auto issue = [&](int kc) {
        const uint32_t bufbase = sb + (uint32_t)(kc & 1) * 4 * TILE_BYTES;
        #pragma unroll
        for (int p = 0; p < 8; p++) {
            int idx = tid + p * GT;
            int tile = idx >> 9, rem = idx & 511;
            int r = rem >> 2, j = rem & 3;
            const __nv_bfloat16* src = gsrc[tile] + (size_t)r * DD + kc * 32 + j * 8;
            uint32_t dst = bufbase + tile * TILE_BYTES + r * TSTR_B + j * 16;
            cpa16(dst, src);
        }
        cpa_commit();
    };

    const int wm = wid >> 2, wn = wid & 3;

    float acc[4][4][4];
    #pragma unroll
    for (int f = 0; f < 4; f++)
        #pragma unroll
        for (int nf = 0; nf < 4; nf++)
            #pragma unroll
            for (int e = 0; e < 4; e++) acc[f][nf][e] = 0.f;

    issue(0);
    for (int kc = 0; kc < 8; kc++) {
        if (kc < 7) { issue(kc + 1); cpa_wait<1>(); }
        else        { cpa_wait<0>(); }
        __syncthreads();

        const uint32_t abase = sb + (uint32_t)(kc & 1) * 4 * TILE_BYTES;
        const uint32_t bbase = abase + 2 * TILE_BYTES;

        #pragma unroll
        for (int s = 0; s < 2; s++) {
            uint32_t bh[8], bl[8];
            {
                int bn = wn * 32 + (lane & 7) + ((lane >> 4) << 3);
                uint32_t bcol = s * 32 + ((lane >> 3) & 1) * 16;
                #pragma unroll
                for (int g = 0; g < 2; g++) {
                    uint32_t addr = bbase + (uint32_t)(bn + g * 16) * TSTR_B + bcol;
                    ldsm4(&bh[g * 4], addr);
                    ldsm4(&bl[g * 4], addr + TILE_BYTES);
                }
            }
            int ar = wm * 64 + (lane & 15);
            uint32_t acol = s * 32 + (lane >> 4) * 16;
            #pragma unroll
            for (int f = 0; f < 4; f++) {
                uint32_t aaddr = abase + (uint32_t)(ar + f * 16) * TSTR_B + acol;
                uint32_t ah[4], al[4];
                ldsm4(ah, aaddr);
                ldsm4(al, aaddr + TILE_BYTES);
                #pragma unroll
                for (int nf = 0; nf < 4; nf++) {
                    mma_bf16(acc[f][nf], ah, &bh[nf * 2]);
                    mma_bf16(acc[f][nf], ah, &bl[nf * 2]);
                    mma_bf16(acc[f][nf], al, &bh[nf * 2]);
                }
            }
        }
        __syncthreads();
    }

    float* obase = g_S + (size_t)(mtile * 128) * NCOLS + ntile * 128;
    const int r0 = wm * 64 + (lane >> 2);
    const int c0 = wn * 32 + (lane & 3) * 2;
    #pragma unroll
    for (int f = 0; f < 4; f++) {
        #pragma unroll
        for (int nf = 0; nf < 4; nf++) {
            int r = r0 + f * 16, cc = c0 + nf * 8;
            float2 v0 = { acc[f][nf][0], acc[f][nf][1] };
            float2 v1 = { acc[f][nf][2], acc[f][nf][3] };
            stcs2(obase + (size_t)r * NCOLS + cc, v0);
            stcs2(obase + (size_t)(r + 8) * NCOLS + cc, v1);
        }
    }
}

// ---------------- epilogue v7b: R15 epi + hoisted rinv registers ----------------
#define ET 256
#define SSTR 52
#define NTILE (RR * SSTR)       // 1872
#define EOFF_G    0                          // 1296
#define EOFF_S    1296                       // 8 * 1872 = 14976
#define EOFF_RINV (EOFF_S + 8*NTILE)         // 288
#define EOFF_RS   (EOFF_RINV + 288)          // 384
#define EOFF_CN   (EOFF_RS + 384)            // 384
#define ESMEM_FLOATS (EOFF_CN + 384)         // 17328 floats = 69312 B

extern __shared__ float esm[];

__global__ void __launch_bounds__(ET, 3) epi_kernel(float* __restrict__ out) {
    const int cg = blockIdx.x;
    const int i  = blockIdx.y;
    const int t  = threadIdx.x;
    const int lane = t & 31, wj = t >> 5;
    const int c0 = cg * 8;

    float* Gs    = esm + EOFF_G;
    float* Stl   = esm + EOFF_S;
    float* rinvS = esm + EOFF_RINV;
    float* rsS   = esm + EOFF_RS;
    float* cnS   = esm + EOFF_CN;
    const uint32_t sbase = smem_u32(esm);

    // ---- group 1: S tile via cp.async ----
    {
        const float* srow = g_S + (size_t)(i * RR) * NCOLS + (size_t)c0 * WW;
        for (int idx = t; idx < RR * 96; idx += ET) {
            int r = idx / 96, rem = idx % 96;
            int j = rem / 12, q = rem % 12;
            cpa16(sbase + (EOFF_S + j * NTILE + r * SSTR + q * 4) * 4,
                  srow + (size_t)r * NCOLS + j * WW + q * 4);
        }
        cpa_commit();
    }
    // ---- group 2: G + capnorms via cp.async ----
    {
        const float* gsrc = g_gram + (size_t)i * RR * RR;
        for (int idx = t; idx < RR * RR / 4; idx += ET)
            cpa16(sbase + (EOFF_G + idx * 4) * 4, gsrc + idx * 4);
        const float* cn = g_capnorm + c0 * WW;
        for (int idx = t; idx < 8 * WW / 4; idx += ET)
            cpa16(sbase + (EOFF_CN + idx * 4) * 4, cn + idx * 4);
        cpa_commit();
    }

    cpa_wait<1>();            // S tile landed
    __syncthreads();

    // ---- rinv9 = 9/(||leaky row||+eps) ----
    for (int row = t; row < 8 * RR; row += ET) {
        int j = row / RR, r = row % RR;
        const float4* sp = (const float4*)(Stl + j * NTILE + r * SSTR);
        float ss = 0.f;
        #pragma unroll
        for (int q = 0; q < 12; q++) {
            float4 a = sp[q];
            float v;
            v = (a.x >= 0.f) ? a.x : 0.1f * a.x; ss = fmaf(v, v, ss);
            v = (a.y >= 0.f) ? a.y : 0.1f * a.y; ss = fmaf(v, v, ss);
            v = (a.z >= 0.f) ? a.z : 0.1f * a.z; ss = fmaf(v, v, ss);
            v = (a.w >= 0.f) ? a.w : 0.1f * a.w; ss = fmaf(v, v, ss);
        }
        rinvS[j * RR + r] = 9.f / (sqrtf(ss) + 1e-8f);
    }
    __syncthreads();

    // ---- per-warp phases; warp wj owns pair (i, c0+wj) ----
    float* Sw = Stl + wj * NTILE;
    const int l3 = lane & 3;
    const int wl = lane >> 2;

    // hoist this lane's 9 rinv values (loop-invariant across the 6 q-iterations)
    float rv9[9];
    {
        const float* rv = rinvS + wj * RR + l3 * 9;
        #pragma unroll
        for (int jj = 0; jj < 9; jj++) rv9[jj] = rv[jj];
    }

    // Phase A: softmax per column; write unnormalized e over S (disjoint cells)
    float s6[6], w126[6];
    #pragma unroll 1
    for (int q = 0; q < 6; q++) {
        const int w = wl * 6 + q;
        float e9[9];
        float s = 0.f, w12p = 0.f;
        #pragma unroll
        for (int jj = 0; jj < 9; jj++) {
            int r = l3 * 9 + jj;
            float sraw = Sw[r * SSTR + w];
            float v = (sraw >= 0.f) ? sraw : 0.1f * sraw;
            float e = __expf(v * rv9[jj]);
            e9[jj] = e;
            s += e;
            w12p = fmaf(e, sraw, w12p);
        }
        s    += __shfl_xor_sync(0xffffffffu, s, 1);
        s    += __shfl_xor_sync(0xffffffffu, s, 2);
        w12p += __shfl_xor_sync(0xffffffffu, w12p, 1);
        w12p += __shfl_xor_sync(0xffffffffu, w12p, 2);
        s6[q] = s;
        w126[q] = w12p;
        #pragma unroll
        for (int jj = 0; jj < 9; jj++)
            Sw[(l3 * 9 + jj) * SSTR + w] = e9[jj];
    }
    cpa_wait<0>();            // G + cn landed (overlapped with rinv + phase A)
    __syncthreads();

    // Phase B/C split into two jj-halves (register cap, 3 CTAs/SM)
    u64 w2p[3] = {0ull, 0ull, 0ull};

    // ---- half 1: jj in [0,5) ----
    {
        u64 acc[5][3];
        #pragma unroll
        for (int jj = 0; jj < 5; jj++)
            #pragma unroll
            for (int p = 0; p < 3; p++) acc[jj][p] = 0ull;

        #pragma unroll 4
        for (int l = 0; l < RR; l++) {
            const float* Erow = Sw + l * SSTR + wl * 6;
            u64 ep0 = *(const u64*)(Erow);
            u64 ep1 = *(const u64*)(Erow + 2);
            u64 ep2 = *(const u64*)(Erow + 4);
            const float* gcol = Gs + (l3 * 9) * RR + l;
            #pragma unroll
            for (int jj = 0; jj < 5; jj++) {
                u64 g2 = dup2(gcol[jj * RR]);
                ffma2(acc[jj][0], g2, ep0);
                ffma2(acc[jj][1], g2, ep1);
                ffma2(acc[jj][2], g2, ep2);
            }
        }
        #pragma unroll
        for (int jj = 0; jj < 5; jj++) {
            const float* Ek = Sw + (l3 * 9 + jj) * SSTR + wl * 6;
            ffma2(w2p[0], *(const u64*)(Ek),     acc[jj][0]);
            ffma2(w2p[1], *(const u64*)(Ek + 2), acc[jj][1]);
            ffma2(w2p[2], *(const u64*)(Ek + 4), acc[jj][2]);
        }
    }
    // ---- half 2: jj in [5,9) ----
    {
        u64 acc[4][3];
        #pragma unroll
        for (int jj = 0; jj < 4; jj++)
            #pragma unroll
            for (int p = 0; p < 3; p++) acc[jj][p] = 0ull;

        #pragma unroll 4
        for (int l = 0; l < RR; l++) {
            const float* Erow = Sw + l * SSTR + wl * 6;
            u64 ep0 = *(const u64*)(Erow);
            u64 ep1 = *(const u64*)(Erow + 2);
            u64 ep2 = *(const u64*)(Erow + 4);
            const float* gcol = Gs + (l3 * 9 + 5) * RR + l;
            #pragma unroll
            for (int jj = 0; jj < 4; jj++) {
                u64 g2 = dup2(gcol[jj * RR]);
                ffma2(acc[jj][0], g2, ep0);
                ffma2(acc[jj][1], g2, ep1);
                ffma2(acc[jj][2], g2, ep2);
            }
        }
        #pragma unroll
        for (int jj = 0; jj < 4; jj++) {
            const float* Ek = Sw + (l3 * 9 + 5 + jj) * SSTR + wl * 6;
            ffma2(w2p[0], *(const u64*)(Ek),     acc[jj][0]);
            ffma2(w2p[1], *(const u64*)(Ek + 2), acc[jj][1]);
            ffma2(w2p[2], *(const u64*)(Ek + 4), acc[jj][2]);
        }
    }

    float w2[6];
    {
        float2 a = unpk(w2p[0]), b = unpk(w2p[1]), c = unpk(w2p[2]);
        w2[0] = a.x; w2[1] = a.y; w2[2] = b.x; w2[3] = b.y; w2[4] = c.x; w2[5] = c.y;
    }
    #pragma unroll
    for (int q = 0; q < 6; q++) {
        w2[q] += __shfl_xor_sync(0xffffffffu, w2[q], 1);
        w2[q] += __shfl_xor_sync(0xffffffffu, w2[q], 2);
    }

    if (l3 == 0) {
        #pragma unroll
        for (int q = 0; q < 6; q++) {
            const int w = wl * 6 + q;
            float is = 1.f / s6[q];
            float w12v = w126[q] * is;
            float w2v = sqrtf(fmaxf(w2[q], 0.f)) * is;
            float denom = fmaxf(cnS[wj * WW + w] * w2v, 1e-8f);
            rsS[wj * WW + w] = (w12v / denom) * 6.f;
        }
    }
    __syncwarp();

    // ---- per-warp LogSumExp over 48 words ----
    {
        const float* r = rsS + wj * WW;
        float s = __expf(r[lane]);
        if (lane < 16) s += __expf(r[32 + lane]);
        #pragma unroll
        for (int off = 16; off; off >>= 1)
            s += __shfl_xor_sync(0xffffffffu, s, off);
        if (lane == 0)
            out[(size_t)i * NC + (c0 + wj)] = logf(s) * (1.f / 6.f);
    }
}

extern "C" void kernel_launch(void* const* d_in, const int* in_sizes, int n_in,
                              void* d_out, int out_size)
{
    const float* images   = (const float*)d_in[0];   // (128, 36, 256) fp32
    const float* captions = (const float*)d_in[1];   // (256, 48, 256) fp32
    float* out = (float*)d_out;                       // (128, 256) fp32

    decomp_kernel<<<512, 256>>>(images, captions);
    capnorm_kernel<<<NCOLS / 8, 256>>>(captions);
    gram_kernel<<<NI, 256>>>(images);

    cudaFuncSetAttribute(gemm_kernel,
                         cudaFuncAttributeMaxDynamicSharedMemorySize, GSMEM_TOTAL);
    dim3 ggrid(NCOLS / 128, MROWS / 128);   // 96 x 36
    gemm_kernel<<<ggrid, GT, GSMEM_TOTAL>>>();

    cudaFuncSetAttribute(epi_kernel,
                         cudaFuncAttributeMaxDynamicSharedMemorySize,
                         ESMEM_FLOATS * (int)sizeof(float));
    dim3 egrid(NC / 8, NI);                 // 32 x 128
    epi_kernel<<<egrid, ET, ESMEM_FLOATS * sizeof(float)>>>(out);
}